// round 15
// baseline (speedup 1.0000x reference)
#include <cuda_runtime.h>
#include <cuda_bf16.h>
#include <cuda_fp16.h>
#include <cstdint>

// Problem constants
#define BB 8
#define SS 1024
#define DD 512
#define HH 8
#define HD 64
#define FF 2048
#define NROWS (BB*SS)          // 8192
#define L2E 1.4426950408889634f

// ---------------- helpers ----------------------------------------------------
__device__ __forceinline__ uint32_t smem_to_u32(const void* p) {
    uint32_t a;
    asm("{ .reg .u64 t; cvta.to.shared.u64 t, %1; cvt.u32.u64 %0, t; }"
        : "=r"(a) : "l"(p));
    return a;
}
__device__ __forceinline__ void cpasync16(uint32_t s, const void* g) {
    asm volatile("cp.async.cg.shared.global [%0], [%1], 16;" :: "r"(s), "l"(g));
}
__device__ __forceinline__ void cpasync_commit() {
    asm volatile("cp.async.commit_group;" ::: "memory");
}
__device__ __forceinline__ void cpasync_wait1() {
    asm volatile("cp.async.wait_group 1;" ::: "memory");
}
__device__ __forceinline__ void cpasync_wait0() {
    asm volatile("cp.async.wait_group 0;" ::: "memory");
}
__device__ __forceinline__ void ldsm4(uint32_t* r, uint32_t addr) {
    asm volatile("ldmatrix.sync.aligned.m8n8.x4.shared.b16 {%0,%1,%2,%3}, [%4];"
        : "=r"(r[0]), "=r"(r[1]), "=r"(r[2]), "=r"(r[3]) : "r"(addr));
}
__device__ __forceinline__ void ldsm4t(uint32_t* r, uint32_t addr) {
    asm volatile("ldmatrix.sync.aligned.m8n8.x4.trans.shared.b16 {%0,%1,%2,%3}, [%4];"
        : "=r"(r[0]), "=r"(r[1]), "=r"(r[2]), "=r"(r[3]) : "r"(addr));
}
__device__ __forceinline__ void mma16816(float* c, const uint32_t* a, const uint32_t* b) {
    asm volatile(
        "mma.sync.aligned.m16n8k16.row.col.f32.bf16.bf16.f32 "
        "{%0,%1,%2,%3}, {%4,%5,%6,%7}, {%8,%9}, {%0,%1,%2,%3};"
        : "+f"(c[0]), "+f"(c[1]), "+f"(c[2]), "+f"(c[3])
        : "r"(a[0]), "r"(a[1]), "r"(a[2]), "r"(a[3]), "r"(b[0]), "r"(b[1]));
}
__device__ __forceinline__ void mma16816h(float* c, const uint32_t* a, const uint32_t* b) {
    asm volatile(
        "mma.sync.aligned.m16n8k16.row.col.f32.f16.f16.f32 "
        "{%0,%1,%2,%3}, {%4,%5,%6,%7}, {%8,%9}, {%0,%1,%2,%3};"
        : "+f"(c[0]), "+f"(c[1]), "+f"(c[2]), "+f"(c[3])
        : "r"(a[0]), "r"(a[1]), "r"(a[2]), "r"(a[3]), "r"(b[0]), "r"(b[1]));
}
__device__ __forceinline__ void split_bf16(float v, __nv_bfloat16& h, __nv_bfloat16& l) {
    h = __float2bfloat16_rn(v);
    l = __float2bfloat16_rn(v - __bfloat162float(h));
}
__device__ __forceinline__ uint32_t packh(float x0, float x1) {
    uint32_t r;
    asm("cvt.rn.f16x2.f32 %0, %1, %2;" : "=r"(r) : "f"(x1), "f"(x0));
    return r;
}
__device__ __forceinline__ uint32_t ex2h2(uint32_t v) {
    uint32_t r;
    asm("ex2.approx.f16x2 %0, %1;" : "=r"(r) : "r"(v));
    return r;
}
__device__ __forceinline__ float ex2f(float x) {
    float r;
    asm("ex2.approx.f32 %0, %1;" : "=f"(r) : "f"(x));
    return r;
}

// ---------------- scratch (device globals) ----------------------------------
__device__ __nv_bfloat16 g_hhi [NROWS*DD], g_hlo [NROWS*DD];
__device__ __half        g_hh16[NROWS*DD];
__device__ __nv_bfloat16 g_qhi [NROWS*DD], g_qlo [NROWS*DD];
__device__ __nv_bfloat16 g_khi [NROWS*DD], g_klo [NROWS*DD];
__device__ __half        g_vh  [NROWS*DD];
__device__ __half        g_ch  [NROWS*DD];
__device__ float         g_x2  [NROWS*DD];
__device__ __half        g_h2h [NROWS*DD];
__device__ __half        g_ffh [NROWS*FF];
__device__ __nv_bfloat16 g_wqhi[DD*DD], g_wqlo[DD*DD];
__device__ __nv_bfloat16 g_wkhi[DD*DD], g_wklo[DD*DD];
__device__ __half        g_wv16[DD*DD];
__device__ __half        g_wo16[DD*DD];
__device__ __half        g_w1h [FF*DD];
__device__ __half        g_w2h [DD*FF];

// ---------------- weight conversions -----------------------------------------
struct CvtArgs2 {
    const float* s[2];
    __nv_bfloat16* h[2];
    __nv_bfloat16* l[2];
    float scale[2];
};
__global__ __launch_bounds__(256) void cvt2_kernel(CvtArgs2 a)
{
    int w = blockIdx.y;
    int i = blockIdx.x * 256 + threadIdx.x;
    float sc = a.scale[w];
    float4 v = ((const float4*)a.s[w])[i];
    v.x *= sc; v.y *= sc; v.z *= sc; v.w *= sc;
    __nv_bfloat16 h[4], l[4];
    split_bf16(v.x, h[0], l[0]); split_bf16(v.y, h[1], l[1]);
    split_bf16(v.z, h[2], l[2]); split_bf16(v.w, h[3], l[3]);
    *(uint2*)(a.h[w] + (size_t)i * 4) = *(uint2*)h;
    *(uint2*)(a.l[w] + (size_t)i * 4) = *(uint2*)l;
}
struct CvtArgsH {
    const float* s[4];
    __half* o[4];
    int n4[4];
};
__global__ __launch_bounds__(256) void cvt4h_kernel(CvtArgsH a)
{
    int w = blockIdx.y;
    int i = blockIdx.x * 256 + threadIdx.x;
    if (i >= a.n4[w]) return;
    float4 v = ((const float4*)a.s[w])[i];
    __half o[4];
    o[0] = __float2half_rn(v.x); o[1] = __float2half_rn(v.y);
    o[2] = __float2half_rn(v.z); o[3] = __float2half_rn(v.w);
    *(uint2*)(a.o[w] + (size_t)i * 4) = *(uint2*)o;
}

// ---------------- RMSNorm: writes hi/lo bf16 + fp16 single -------------------
__global__ __launch_bounds__(256) void rmsnorm_kernel(
    const float* __restrict__ x, const float* __restrict__ w,
    __nv_bfloat16* __restrict__ ohi, __nv_bfloat16* __restrict__ olo,
    __half* __restrict__ oh16)
{
    int row = blockIdx.x;
    const float* xr = x + (size_t)row * DD;
    int t = threadIdx.x;
    float v0 = xr[t];
    float v1 = xr[t + 256];
    float ss = v0 * v0 + v1 * v1;
    #pragma unroll
    for (int off = 16; off; off >>= 1)
        ss += __shfl_xor_sync(0xffffffffu, ss, off);
    __shared__ float red[8];
    if ((t & 31) == 0) red[t >> 5] = ss;
    __syncthreads();
    float total = 0.f;
    #pragma unroll
    for (int i = 0; i < 8; i++) total += red[i];
    float inv = rsqrtf(total * (1.0f / DD) + 1e-6f);
    float o0 = w[t] * v0 * inv;
    float o1 = w[t + 256] * v1 * inv;
    __nv_bfloat16 h, l;
    size_t base = (size_t)row * DD;
    split_bf16(o0, h, l); ohi[base + t] = h;       olo[base + t] = l;
    split_bf16(o1, h, l); ohi[base + t + 256] = h; olo[base + t + 256] = l;
    oh16[base + t]       = __float2half_rn(o0);
    oh16[base + t + 256] = __float2half_rn(o1);
}

// ---------------- RMSNorm: writes fp16 single (row-offset version) -----------
__global__ __launch_bounds__(256) void rmsnorm_h_kernel(
    const float* __restrict__ x, const float* __restrict__ w,
    __half* __restrict__ oh, int row0)
{
    int row = row0 + blockIdx.x;
    const float* xr = x + (size_t)row * DD;
    int t = threadIdx.x;
    float v0 = xr[t];
    float v1 = xr[t + 256];
    float ss = v0 * v0 + v1 * v1;
    #pragma unroll
    for (int off = 16; off; off >>= 1)
        ss += __shfl_xor_sync(0xffffffffu, ss, off);
    __shared__ float red[8];
    if ((t & 31) == 0) red[t >> 5] = ss;
    __syncthreads();
    float total = 0.f;
    #pragma unroll
    for (int i = 0; i < 8; i++) total += red[i];
    float inv = rsqrtf(total * (1.0f / DD) + 1e-6f);
    size_t base = (size_t)row * DD;
    oh[base + t]       = __float2half_rn(w[t] * v0 * inv);
    oh[base + t + 256] = __float2half_rn(w[t + 256] * v1 * inv);
}

// ---------------- split-bf16 tensor-core GEMM (mma.sync) ---------------------
// C[M,N] = A[M,K] @ B[N,K]^T -> bf16 hi/lo.  (Q/K projections)
#define STG 65536
#define OFF_ALO 16384
#define OFF_BHI 32768
#define OFF_BLO 49152
#define TSWZ(r, c16) ((uint32_t)((r) * 128 + (((c16) ^ ((r) & 7)) << 4)))

__global__ __launch_bounds__(256) void gemm_mma_kernel(
    const __nv_bfloat16* __restrict__ Ahi, const __nv_bfloat16* __restrict__ Alo,
    const __nv_bfloat16* __restrict__ Bhi, const __nv_bfloat16* __restrict__ Blo,
    __nv_bfloat16* __restrict__ Chi, __nv_bfloat16* __restrict__ Clo,
    int N, int K)
{
    extern __shared__ char smem[];
    uint32_t sb = smem_to_u32(smem);
    int tid = threadIdx.x;
    int wid = tid >> 5, lane = tid & 31;
    int bm = blockIdx.y * 128, bn = blockIdx.x * 128;

    int lr0 = tid >> 3, lc = tid & 7;
    uint32_t soff[4];
    uint32_t ofsA[4], ofsB[4];
    #pragma unroll
    for (int it = 0; it < 4; it++) {
        int r = lr0 + it * 32;
        soff[it] = TSWZ(r, lc);
        ofsA[it] = (uint32_t)((bm + r) * K + lc * 8);
        ofsB[it] = (uint32_t)((bn + r) * K + lc * 8);
    }

    #define ISSUE(s, kt) do {                                                   \
        uint32_t _b = sb + (uint32_t)(s) * STG;                                 \
        uint32_t _ko = (uint32_t)(kt) * 64;                                     \
        _Pragma("unroll")                                                       \
        for (int _it = 0; _it < 4; _it++) {                                     \
            cpasync16(_b + soff[_it],           Ahi + ofsA[_it] + _ko);         \
            cpasync16(_b + OFF_ALO + soff[_it], Alo + ofsA[_it] + _ko);         \
            cpasync16(_b + OFF_BHI + soff[_it], Bhi + ofsB[_it] + _ko);         \
            cpasync16(_b + OFF_BLO + soff[_it], Blo + ofsB[_it] + _ko);         \
        }                                                                       \
        cpasync_commit();                                                       \
    } while (0)

    float acc[2][8][4];
    #pragma unroll
    for (int ma = 0; ma < 2; ma++)
        #pragma unroll
        for (int na = 0; na < 8; na++)
            #pragma unroll
            for (int j = 0; j < 4; j++) acc[ma][na][j] = 0.f;

    int wm = wid & 3, wn = wid >> 2;
    int arow = wm * 32 + (lane & 15);
    int ac16 = lane >> 4;
    int brow = wn * 64 + (lane & 7) + ((lane >> 4) & 1) * 8;
    int bc16 = (lane >> 3) & 1;

    const int NC = K >> 6;
    ISSUE(0, 0);

    #pragma unroll 1
    for (int kt = 0; kt < NC; kt++) {
        if (kt + 1 < NC) { ISSUE((kt + 1) & 1, kt + 1); cpasync_wait1(); }
        else             { cpasync_wait0(); }
        __syncthreads();

        uint32_t ab = sb + (uint32_t)(kt & 1) * STG;
        #pragma unroll
        for (int kk = 0; kk < 4; kk++) {
            uint32_t ah[2][4], al[2][4];
            #pragma unroll
            for (int ma = 0; ma < 2; ma++) {
                uint32_t ad = ab + TSWZ(arow + ma * 16, ac16 + kk * 2);
                ldsm4(ah[ma], ad);
                ldsm4(al[ma], ad + OFF_ALO);
            }
            #pragma unroll
            for (int np = 0; np < 4; np++) {
                uint32_t bd = ab + OFF_BHI + TSWZ(brow + np * 16, bc16 + kk * 2);
                uint32_t bh[4], bl[4];
                ldsm4(bh, bd);
                ldsm4(bl, bd + 16384);
                #pragma unroll
                for (int ma = 0; ma < 2; ma++) {
                    mma16816(acc[ma][np*2],   ah[ma], bh);
                    mma16816(acc[ma][np*2+1], ah[ma], bh + 2);
                    mma16816(acc[ma][np*2],   ah[ma], bl);
                    mma16816(acc[ma][np*2+1], ah[ma], bl + 2);
                    mma16816(acc[ma][np*2],   al[ma], bh);
                    mma16816(acc[ma][np*2+1], al[ma], bh + 2);
                }
            }
        }
        __syncthreads();
    }

    // epilogue
    int g = lane >> 2, tg = lane & 3;
    #pragma unroll
    for (int ma = 0; ma < 2; ma++) {
        #pragma unroll
        for (int na = 0; na < 8; na++) {
            int row = bm + wm * 32 + ma * 16 + g;
            int col = bn + wn * 64 + na * 8 + tg * 2;
            float* c = acc[ma][na];
            size_t o0 = (size_t)row * N + col;
            size_t o1 = (size_t)(row + 8) * N + col;
            __nv_bfloat16 h0[2], l0[2], h1[2], l1[2];
            split_bf16(c[0], h0[0], l0[0]); split_bf16(c[1], h0[1], l0[1]);
            split_bf16(c[2], h1[0], l1[0]); split_bf16(c[3], h1[1], l1[1]);
            *(uint32_t*)(Chi + o0) = *(uint32_t*)h0;
            *(uint32_t*)(Clo + o0) = *(uint32_t*)l0;
            *(uint32_t*)(Chi + o1) = *(uint32_t*)h1;
            *(uint32_t*)(Clo + o1) = *(uint32_t*)l1;
        }
    }
    #undef ISSUE
}

// ---------------- single-fp16 tensor-core GEMM -------------------------------
// EPI: 0 = fp16 out   1 = relu -> fp16   2 = +R -> fp32
// bm0 = row offset (for row-half pipelining)
#define HSTG 32768
#define H_B  16384

template <int EPI>
__global__ __launch_bounds__(256) void gemm_h_kernel(
    const __half* __restrict__ A, const __half* __restrict__ B,
    const float* __restrict__ R, float* __restrict__ Cf,
    __half* __restrict__ Ch, int N, int K, int bm0)
{
    extern __shared__ char smem[];
    uint32_t sb = smem_to_u32(smem);
    int tid = threadIdx.x;
    int wid = tid >> 5, lane = tid & 31;
    int bm = bm0 + blockIdx.y * 128, bn = blockIdx.x * 128;

    int lr0 = tid >> 3, lc = tid & 7;
    uint32_t soff[4];
    uint32_t ofsA[4], ofsB[4];
    #pragma unroll
    for (int it = 0; it < 4; it++) {
        int r = lr0 + it * 32;
        soff[it] = TSWZ(r, lc);
        ofsA[it] = (uint32_t)((bm + r) * K + lc * 8);
        ofsB[it] = (uint32_t)((bn + r) * K + lc * 8);
    }

    #define HISSUE(s, kt) do {                                                  \
        uint32_t _b = sb + (uint32_t)(s) * HSTG;                                \
        uint32_t _ko = (uint32_t)(kt) * 64;                                     \
        _Pragma("unroll")                                                       \
        for (int _it = 0; _it < 4; _it++) {                                     \
            cpasync16(_b + soff[_it],        A + ofsA[_it] + _ko);              \
            cpasync16(_b + H_B + soff[_it],  B + ofsB[_it] + _ko);              \
        }                                                                       \
        cpasync_commit();                                                       \
    } while (0)

    float acc[2][8][4];
    #pragma unroll
    for (int ma = 0; ma < 2; ma++)
        #pragma unroll
        for (int na = 0; na < 8; na++)
            #pragma unroll
            for (int j = 0; j < 4; j++) acc[ma][na][j] = 0.f;

    int wm = wid & 3, wn = wid >> 2;
    int arow = wm * 32 + (lane & 15);
    int ac16 = lane >> 4;
    int brow = wn * 64 + (lane & 7) + ((lane >> 4) & 1) * 8;
    int bc16 = (lane >> 3) & 1;

    const int NC = K >> 6;
    HISSUE(0, 0);

    #pragma unroll 1
    for (int kt = 0; kt < NC; kt++) {
        if (kt + 1 < NC) { HISSUE((kt + 1) & 1, kt + 1); cpasync_wait1(); }
        else             { cpasync_wait0(); }
        __syncthreads();

        uint32_t ab = sb + (uint32_t)(kt & 1) * HSTG;
        #pragma unroll
        for (int kk = 0; kk < 4; kk++) {
            uint32_t ah[2][4];
            #pragma unroll
            for (int ma = 0; ma < 2; ma++)
                ldsm4(ah[ma], ab + TSWZ(arow + ma * 16, ac16 + kk * 2));
            #pragma unroll
            for (int np = 0; np < 4; np++) {
                uint32_t bh[4];
                ldsm4(bh, ab + H_B + TSWZ(brow + np * 16, bc16 + kk * 2));
                #pragma unroll
                for (int ma = 0; ma < 2; ma++) {
                    mma16816h(acc[ma][np*2],   ah[ma], bh);
                    mma16816h(acc[ma][np*2+1], ah[ma], bh + 2);
                }
            }
        }
        __syncthreads();
    }

    // epilogue
    int g = lane >> 2, tg = lane & 3;
    #pragma unroll
    for (int ma = 0; ma < 2; ma++) {
        #pragma unroll
        for (int na = 0; na < 8; na++) {
            int row = bm + wm * 32 + ma * 16 + g;
            int col = bn + wn * 64 + na * 8 + tg * 2;
            float* c = acc[ma][na];
            size_t o0 = (size_t)row * N + col;
            size_t o1 = (size_t)(row + 8) * N + col;
            if (EPI == 0 || EPI == 1) {
                float v0 = c[0], v1 = c[1], v2 = c[2], v3 = c[3];
                if (EPI == 1) {
                    v0 = fmaxf(v0, 0.f); v1 = fmaxf(v1, 0.f);
                    v2 = fmaxf(v2, 0.f); v3 = fmaxf(v3, 0.f);
                }
                __half h0[2], h1[2];
                h0[0] = __float2half_rn(v0); h0[1] = __float2half_rn(v1);
                h1[0] = __float2half_rn(v2); h1[1] = __float2half_rn(v3);
                *(uint32_t*)(Ch + o0) = *(uint32_t*)h0;
                *(uint32_t*)(Ch + o1) = *(uint32_t*)h1;
            } else {
                float2 v0 = make_float2(c[0], c[1]);
                float2 v1 = make_float2(c[2], c[3]);
                float2 r0 = *(const float2*)(R + o0);
                float2 r1 = *(const float2*)(R + o1);
                v0.x += r0.x; v0.y += r0.y;
                v1.x += r1.x; v1.y += r1.y;
                *(float2*)(Cf + o0) = v0;
                *(float2*)(Cf + o1) = v1;
            }
        }
    }
    #undef HISSUE
}

// ---------------- tensor-core flash attention --------------------------------
// Q bf16 hi/lo (pre-scaled log2e), K bf16 hi/lo, V fp16 single,
// ctx fp16 single. Bias direct LDG. SMEM 80 KB -> 2 CTAs/SM.
#define AQ_HI 0u
#define AQ_LO 16384u
#define AKV0  32768u
#define AKV_STG 24576u
#define A_SMEM (32768u + 2u*24576u)

__global__ __launch_bounds__(256, 2) void attn_mma_kernel(
    const __nv_bfloat16* __restrict__ Qhi, const __nv_bfloat16* __restrict__ Qlo,
    const __nv_bfloat16* __restrict__ Khi, const __nv_bfloat16* __restrict__ Klo,
    const __half* __restrict__ Vh,
    const float* __restrict__ bias,
    __half* __restrict__ ch)
{
    extern __shared__ char smem[];
    uint32_t sb = smem_to_u32(smem);
    int tid = threadIdx.x, wid = tid >> 5, lane = tid & 31;
    int qt = blockIdx.x, h = blockIdx.y, b = blockIdx.z;

    // ---- Q load ----
    {
        int r = tid >> 1;
        int cb = (tid & 1) * 4;
        size_t grow = ((size_t)(b * SS + qt * 128 + r)) * DD + h * HD;
        #pragma unroll
        for (int i = 0; i < 4; i++) {
            int c16 = cb + i;
            uint32_t so = TSWZ(r, c16);
            cpasync16(sb + AQ_HI + so, Qhi + grow + c16 * 8);
            cpasync16(sb + AQ_LO + so, Qlo + grow + c16 * 8);
        }
        cpasync_commit();
    }
    // ---- KV tile issue ----
    int kvr = tid & 63;
    int kvcb = (tid >> 6) * 2;
    #define ISSUE_KV(kt, stg) do {                                              \
        uint32_t _bse = sb + AKV0 + (uint32_t)(stg) * AKV_STG;                  \
        size_t _gr = ((size_t)(b * SS + (kt) * 64 + kvr)) * DD + h * HD;        \
        _Pragma("unroll")                                                       \
        for (int _i = 0; _i < 2; _i++) {                                        \
            int _c = kvcb + _i;                                                 \
            uint32_t _so = TSWZ(kvr, _c);                                       \
            cpasync16(_bse + _so,          Khi + _gr + _c * 8);                 \
            cpasync16(_bse + 8192 + _so,   Klo + _gr + _c * 8);                 \
            cpasync16(_bse + 16384 + _so,  Vh  + _gr + _c * 8);                 \
        }                                                                       \
        cpasync_commit();                                                       \
    } while (0)

    ISSUE_KV(0, 0);

    float oacc[8][4];
    #pragma unroll
    for (int na = 0; na < 8; na++)
        #pragma unroll
        for (int j = 0; j < 4; j++) oacc[na][j] = 0.f;
    float lacc[4] = {0.f, 0.f, 0.f, 0.f};
    float m0 = -1e30f, m1 = -1e30f;
    const uint32_t bones[2] = {0x3C003C00u, 0x3C003C00u};

    int arow = wid * 16 + (lane & 15);
    int ac16 = lane >> 4;
    int bro  = (lane & 7) + ((lane >> 4) & 1) * 8;
    int bc16 = (lane >> 3) & 1;
    int vro  = lane & 15;
    int vch  = lane >> 4;

    size_t brow0 = ((size_t)(b * HH + h) * SS + (qt * 128 + wid * 16 + (lane >> 2))) * SS
                   + 2 * (lane & 3);
    size_t brow1 = brow0 + 8 * (size_t)SS;

    #pragma unroll 1
    for (int kt = 0; kt < 16; kt++) {
        if (kt + 1 < 16) { ISSUE_KV(kt + 1, (kt + 1) & 1); cpasync_wait1(); }
        else             { cpasync_wait0(); }
        __syncthreads();
        uint32_t kvb = sb + AKV0 + (uint32_t)(kt & 1) * AKV_STG;

        // ---- S = Q K^T (split: 3 terms) ----
        float sacc[8][4];
        #pragma unroll
        for (int na = 0; na < 8; na++)
            #pragma unroll
            for (int j = 0; j < 4; j++) sacc[na][j] = 0.f;
        #pragma unroll
        for (int kk = 0; kk < 4; kk++) {
            uint32_t ah[4], al[4];
            uint32_t ad = sb + AQ_HI + TSWZ(arow, ac16 + kk * 2);
            ldsm4(ah, ad);
            ldsm4(al, ad + AQ_LO);
            #pragma unroll
            for (int ng = 0; ng < 4; ng++) {
                uint32_t bd = kvb + TSWZ(bro + ng * 16, bc16 + kk * 2);
                uint32_t kh[4], kl[4];
                ldsm4(kh, bd);
                ldsm4(kl, bd + 8192);
                mma16816(sacc[ng*2],   ah, kh);
                mma16816(sacc[ng*2+1], ah, kh + 2);
                mma16816(sacc[ng*2],   ah, kl);
                mma16816(sacc[ng*2+1], ah, kl + 2);
                mma16816(sacc[ng*2],   al, kh);
                mma16816(sacc[ng*2+1], al, kh + 2);
            }
        }

        // ---- bias (x log2e) + max ----
        const float* bp0 = bias + brow0 + kt * 64;
        const float* bp1 = bias + brow1 + kt * 64;
        float tm0 = -1e30f, tm1 = -1e30f;
        #pragma unroll
        for (int na = 0; na < 8; na++) {
            float2 bv0 = *(const float2*)(bp0 + na * 8);
            float2 bv1 = *(const float2*)(bp1 + na * 8);
            sacc[na][0] = fmaf(bv0.x, L2E, sacc[na][0]);
            sacc[na][1] = fmaf(bv0.y, L2E, sacc[na][1]);
            sacc[na][2] = fmaf(bv1.x, L2E, sacc[na][2]);
            sacc[na][3] = fmaf(bv1.y, L2E, sacc[na][3]);
            tm0 = fmaxf(tm0, fmaxf(sacc[na][0], sacc[na][1]));
            tm1 = fmaxf(tm1, fmaxf(sacc[na][2], sacc[na][3]));
        }
        tm0 = fmaxf(tm0, __shfl_xor_sync(0xffffffffu, tm0, 1));
        tm0 = fmaxf(tm0, __shfl_xor_sync(0xffffffffu, tm0, 2));
        tm1 = fmaxf(tm1, __shfl_xor_sync(0xffffffffu, tm1, 1));
        tm1 = fmaxf(tm1, __shfl_xor_sync(0xffffffffu, tm1, 2));
        float mn0 = fmaxf(m0, tm0), mn1 = fmaxf(m1, tm1);

        if (mn0 != m0 || mn1 != m1) {
            float c0 = ex2f(m0 - mn0), c1 = ex2f(m1 - mn1);
            #pragma unroll
            for (int na = 0; na < 8; na++) {
                oacc[na][0] *= c0; oacc[na][1] *= c0;
                oacc[na][2] *= c1; oacc[na][3] *= c1;
            }
            lacc[0] *= c0; lacc[2] *= c1;
            m0 = mn0; m1 = mn1;
        }

        // ---- p = 2^(t - m) via f16x2; results are P fp16 A-fragments ----
        uint32_t pf[4][4];
        #pragma unroll
        for (int kk = 0; kk < 4; kk++) {
            int n0 = 2 * kk, n1 = 2 * kk + 1;
            pf[kk][0] = ex2h2(packh(sacc[n0][0] - mn0, sacc[n0][1] - mn0));
            pf[kk][1] = ex2h2(packh(sacc[n0][2] - mn1, sacc[n0][3] - mn1));
            pf[kk][2] = ex2h2(packh(sacc[n1][0] - mn0, sacc[n1][1] - mn0));
            pf[kk][3] = ex2h2(packh(sacc[n1][2] - mn1, sacc[n1][3] - mn1));
        }

        // ---- l += row-sums of P ----
        #pragma unroll
        for (int kk = 0; kk < 4; kk++)
            mma16816h(lacc, pf[kk], bones);

        // ---- O += P V (V fp16 single, 1 term) ----
        #pragma unroll
        for (int kk = 0; kk < 4; kk++) {
            #pragma unroll
            for (int j = 0; j < 4; j++) {
                uint32_t vd = kvb + 16384 + TSWZ(kk * 16 + vro, 2 * j + vch);
                uint32_t vh[4];
                ldsm4t(vh, vd);
                mma16816h(oacc[j*2],   pf[kk], vh);
                mma16816h(oacc[j*2+1], pf[kk], vh + 2);
            }
        }
        __syncthreads();
    }

    // ---- epilogue: ctx = O / l, write fp16 single ----
    float il0 = 1.0f / lacc[0], il1 = 1.0f / lacc[2];
    int row0 = b * SS + qt * 128 + wid * 16 + (lane >> 2);
    int colb = h * HD + 2 * (lane & 3);
    #pragma unroll
    for (int na = 0; na < 8; na++) {
        size_t o0 = (size_t)row0 * DD + colb + na * 8;
        size_t o1 = o0 + 8 * (size_t)DD;
        __half hh[2];
        hh[0] = __float2half_rn(oacc[na][0] * il0);
        hh[1] = __float2half_rn(oacc[na][1] * il0);
        *(uint32_t*)(ch + o0) = *(uint32_t*)hh;
        hh[0] = __float2half_rn(oacc[na][2] * il1);
        hh[1] = __float2half_rn(oacc[na][3] * il1);
        *(uint32_t*)(ch + o1) = *(uint32_t*)hh;
    }
    #undef ISSUE_KV
}

// ---------------- stream/event context (created at static init, pre-harness) -
struct StreamCtx {
    cudaStream_t s1 = 0, s2 = 0;
    cudaEvent_t e0 = 0, eR = 0, eC4 = 0, eC2 = 0, eK = 0, eV = 0, eA = 0, eB = 0;
    bool ok = false;
    StreamCtx() {
        ok = cudaStreamCreateWithFlags(&s1, cudaStreamNonBlocking) == cudaSuccess
          && cudaStreamCreateWithFlags(&s2, cudaStreamNonBlocking) == cudaSuccess
          && cudaEventCreateWithFlags(&e0,  cudaEventDisableTiming) == cudaSuccess
          && cudaEventCreateWithFlags(&eR,  cudaEventDisableTiming) == cudaSuccess
          && cudaEventCreateWithFlags(&eC4, cudaEventDisableTiming) == cudaSuccess
          && cudaEventCreateWithFlags(&eC2, cudaEventDisableTiming) == cudaSuccess
          && cudaEventCreateWithFlags(&eK,  cudaEventDisableTiming) == cudaSuccess
          && cudaEventCreateWithFlags(&eV,  cudaEventDisableTiming) == cudaSuccess
          && cudaEventCreateWithFlags(&eA,  cudaEventDisableTiming) == cudaSuccess
          && cudaEventCreateWithFlags(&eB,  cudaEventDisableTiming) == cudaSuccess;
    }
};
static StreamCtx g_sc;

// ---------------- launch -----------------------------------------------------
extern "C" void kernel_launch(void* const* d_in, const int* in_sizes, int n_in,
                              void* d_out, int out_size)
{
    const float* Wk   = (const float*)d_in[0];
    const float* Wo   = (const float*)d_in[1];
    const float* Wq   = (const float*)d_in[2];
    const float* Wv   = (const float*)d_in[3];
    const float* ln1  = (const float*)d_in[4];
    const float* W1   = (const float*)d_in[5];
    const float* W2   = (const float*)d_in[6];
    const float* ln2  = (const float*)d_in[7];
    const float* x    = (const float*)d_in[8];
    const float* bias = (const float*)d_in[9];
    float* out = (float*)d_out;

    #define SYM(p, s) void* p; cudaGetSymbolAddress(&p, s)
    SYM(hhi, g_hhi);  SYM(hlo, g_hlo);  SYM(hh16, g_hh16);
    SYM(qhi, g_qhi);  SYM(qlo, g_qlo);
    SYM(khi, g_khi);  SYM(klo, g_klo);
    SYM(vh, g_vh);    SYM(ch, g_ch);
    SYM(px2, g_x2);
    SYM(h2h, g_h2h);  SYM(ffh, g_ffh);
    SYM(wqh, g_wqhi); SYM(wql, g_wqlo);
    SYM(wkh, g_wkhi); SYM(wkl, g_wklo);
    SYM(wv16, g_wv16); SYM(wo16, g_wo16);
    SYM(w1h, g_w1h);  SYM(w2h, g_w2h);
    #undef SYM

    static bool attr_set = false;
    if (!attr_set) {
        cudaFuncSetAttribute(gemm_mma_kernel, cudaFuncAttributeMaxDynamicSharedMemorySize, 2*STG);
        cudaFuncSetAttribute(gemm_h_kernel<0>, cudaFuncAttributeMaxDynamicSharedMemorySize, 2*HSTG);
        cudaFuncSetAttribute(gemm_h_kernel<1>, cudaFuncAttributeMaxDynamicSharedMemorySize, 2*HSTG);
        cudaFuncSetAttribute(gemm_h_kernel<2>, cudaFuncAttributeMaxDynamicSharedMemorySize, 2*HSTG);
        cudaFuncSetAttribute(attn_mma_kernel, cudaFuncAttributeMaxDynamicSharedMemorySize, A_SMEM);
        attr_set = true;
    }

    typedef const __nv_bfloat16* cbf;
    typedef __nv_bfloat16* bf;
    typedef const __half* chf;
    typedef __half* hf;

    cudaStream_t s1 = g_sc.ok ? g_sc.s1 : 0;
    cudaStream_t s2 = g_sc.ok ? g_sc.s2 : 0;
    #define REC(ev, st)  do { if (g_sc.ok) cudaEventRecord(g_sc.ev, st); } while (0)
    #define WAITE(st, ev) do { if (g_sc.ok) cudaStreamWaitEvent(st, g_sc.ev, 0); } while (0)

    // fork
    REC(e0, 0);
    WAITE(s1, e0);
    WAITE(s2, e0);

    // cvt2 (Wq*log2e / Wk, split bf16) on s1; cvt4h (W1/W2/Wo/Wv fp16) on s2;
    // rmsnorm1 on 0 (emits bf16 hi/lo + fp16)
    CvtArgs2 c2;
    c2.s[0] = Wq; c2.h[0] = (bf)wqh; c2.l[0] = (bf)wql; c2.scale[0] = L2E;
    c2.s[1] = Wk; c2.h[1] = (bf)wkh; c2.l[1] = (bf)wkl; c2.scale[1] = 1.0f;
    dim3 g2(DD*DD/4/256, 2);
    cvt2_kernel<<<g2, 256, 0, s1>>>(c2);
    CvtArgsH ch4;
    ch4.s[0] = W1; ch4.o[0] = (hf)w1h;  ch4.n4[0] = FF*DD/4;
    ch4.s[1] = W2; ch4.o[1] = (hf)w2h;  ch4.n4[1] = DD*FF/4;
    ch4.s[2] = Wo; ch4.o[2] = (hf)wo16; ch4.n4[2] = DD*DD/4;
    ch4.s[3] = Wv; ch4.o[3] = (hf)wv16; ch4.n4[3] = DD*DD/4;
    dim3 gh(FF*DD/4/256, 4);
    cvt4h_kernel<<<gh, 256, 0, s2>>>(ch4);
    rmsnorm_kernel<<<NROWS, 256>>>(x, ln1, (bf)hhi, (bf)hlo, (hf)hh16);
    REC(eR, 0);
    REC(eC4, s1);
    REC(eC2, s2);

    // QKV: Q on 0 (needs cvt2), K on s1 (needs rmsnorm), V on s2 (needs rmsnorm)
    WAITE(0, eC4);
    WAITE(s1, eR);
    WAITE(s2, eR);
    dim3 gD(DD/128, NROWS/128);
    gemm_mma_kernel<<<gD, 256, 2*STG, 0>>>((cbf)hhi, (cbf)hlo, (cbf)wqh, (cbf)wql,
                                           (bf)qhi, (bf)qlo, DD, DD);
    gemm_mma_kernel<<<gD, 256, 2*STG, s1>>>((cbf)hhi, (cbf)hlo, (cbf)wkh, (cbf)wkl,
                                            (bf)khi, (bf)klo, DD, DD);
    gemm_h_kernel<0><<<gD, 256, 2*HSTG, s2>>>((chf)hh16, (chf)wv16,
                                              nullptr, nullptr, (hf)vh, DD, DD, 0);
    REC(eK, s1);
    REC(eV, s2);
    WAITE(0, eK);
    WAITE(0, eV);

    // attention -> ctx fp16 single (2 CTAs/SM)
    dim3 ga(SS/128, HH, BB);
    attn_mma_kernel<<<ga, 256, A_SMEM>>>((cbf)qhi, (cbf)qlo, (cbf)khi, (cbf)klo,
                                         (chf)vh, bias, (hf)ch);
    REC(eA, 0);

    // ---- back half: two independent row-half chains (rows 0..4095 on stream0,
    //      rows 4096..8191 on s1). All four ops are row-local. ----
    WAITE(0, eC2);      // Wo/W1/W2 weights ready
    WAITE(s1, eA);      // chain b needs ctx
    WAITE(s1, eC2);

    dim3 gDh(DD/128, NROWS/256);   // (4, 32)
    dim3 gFh(FF/128, NROWS/256);   // (16, 32)
    const int HROWS = NROWS / 2;

    // chain a (rows 0..4095) on stream 0
    gemm_h_kernel<2><<<gDh, 256, 2*HSTG, 0>>>((chf)ch, (chf)wo16,
                                              x, (float*)px2, nullptr, DD, DD, 0);
    rmsnorm_h_kernel<<<HROWS, 256, 0, 0>>>((const float*)px2, ln2, (hf)h2h, 0);
    gemm_h_kernel<1><<<gFh, 256, 2*HSTG, 0>>>((chf)h2h, (chf)w1h,
                                              nullptr, nullptr, (hf)ffh, FF, DD, 0);
    gemm_h_kernel<2><<<gDh, 256, 2*HSTG, 0>>>((chf)ffh, (chf)w2h,
                                              (const float*)px2, out, nullptr, DD, FF, 0);

    // chain b (rows 4096..8191) on s1
    gemm_h_kernel<2><<<gDh, 256, 2*HSTG, s1>>>((chf)ch, (chf)wo16,
                                               x, (float*)px2, nullptr, DD, DD, HROWS);
    rmsnorm_h_kernel<<<HROWS, 256, 0, s1>>>((const float*)px2, ln2, (hf)h2h, HROWS);
    gemm_h_kernel<1><<<gFh, 256, 2*HSTG, s1>>>((chf)h2h, (chf)w1h,
                                               nullptr, nullptr, (hf)ffh, FF, DD, HROWS);
    gemm_h_kernel<2><<<gDh, 256, 2*HSTG, s1>>>((chf)ffh, (chf)w2h,
                                               (const float*)px2, out, nullptr, DD, FF, HROWS);

    // join
    REC(eB, s1);
    WAITE(0, eB);
    #undef REC
    #undef WAITE
}

// round 16
// speedup vs baseline: 1.0165x; 1.0165x over previous
#include <cuda_runtime.h>
#include <cuda_bf16.h>
#include <cuda_fp16.h>
#include <cstdint>

// Problem constants
#define BB 8
#define SS 1024
#define DD 512
#define HH 8
#define HD 64
#define FF 2048
#define NROWS (BB*SS)          // 8192
#define L2E 1.4426950408889634f

// ---------------- helpers ----------------------------------------------------
__device__ __forceinline__ uint32_t smem_to_u32(const void* p) {
    uint32_t a;
    asm("{ .reg .u64 t; cvta.to.shared.u64 t, %1; cvt.u32.u64 %0, t; }"
        : "=r"(a) : "l"(p));
    return a;
}
__device__ __forceinline__ void cpasync16(uint32_t s, const void* g) {
    asm volatile("cp.async.cg.shared.global [%0], [%1], 16;" :: "r"(s), "l"(g));
}
__device__ __forceinline__ void cpasync_commit() {
    asm volatile("cp.async.commit_group;" ::: "memory");
}
__device__ __forceinline__ void cpasync_wait1() {
    asm volatile("cp.async.wait_group 1;" ::: "memory");
}
__device__ __forceinline__ void cpasync_wait0() {
    asm volatile("cp.async.wait_group 0;" ::: "memory");
}
__device__ __forceinline__ void ldsm4(uint32_t* r, uint32_t addr) {
    asm volatile("ldmatrix.sync.aligned.m8n8.x4.shared.b16 {%0,%1,%2,%3}, [%4];"
        : "=r"(r[0]), "=r"(r[1]), "=r"(r[2]), "=r"(r[3]) : "r"(addr));
}
__device__ __forceinline__ void ldsm4t(uint32_t* r, uint32_t addr) {
    asm volatile("ldmatrix.sync.aligned.m8n8.x4.trans.shared.b16 {%0,%1,%2,%3}, [%4];"
        : "=r"(r[0]), "=r"(r[1]), "=r"(r[2]), "=r"(r[3]) : "r"(addr));
}
__device__ __forceinline__ void mma16816(float* c, const uint32_t* a, const uint32_t* b) {
    asm volatile(
        "mma.sync.aligned.m16n8k16.row.col.f32.bf16.bf16.f32 "
        "{%0,%1,%2,%3}, {%4,%5,%6,%7}, {%8,%9}, {%0,%1,%2,%3};"
        : "+f"(c[0]), "+f"(c[1]), "+f"(c[2]), "+f"(c[3])
        : "r"(a[0]), "r"(a[1]), "r"(a[2]), "r"(a[3]), "r"(b[0]), "r"(b[1]));
}
__device__ __forceinline__ void mma16816h(float* c, const uint32_t* a, const uint32_t* b) {
    asm volatile(
        "mma.sync.aligned.m16n8k16.row.col.f32.f16.f16.f32 "
        "{%0,%1,%2,%3}, {%4,%5,%6,%7}, {%8,%9}, {%0,%1,%2,%3};"
        : "+f"(c[0]), "+f"(c[1]), "+f"(c[2]), "+f"(c[3])
        : "r"(a[0]), "r"(a[1]), "r"(a[2]), "r"(a[3]), "r"(b[0]), "r"(b[1]));
}
__device__ __forceinline__ void split_bf16(float v, __nv_bfloat16& h, __nv_bfloat16& l) {
    h = __float2bfloat16_rn(v);
    l = __float2bfloat16_rn(v - __bfloat162float(h));
}
__device__ __forceinline__ uint32_t packh(float x0, float x1) {
    uint32_t r;
    asm("cvt.rn.f16x2.f32 %0, %1, %2;" : "=r"(r) : "f"(x1), "f"(x0));
    return r;
}
__device__ __forceinline__ uint32_t ex2h2(uint32_t v) {
    uint32_t r;
    asm("ex2.approx.f16x2 %0, %1;" : "=r"(r) : "r"(v));
    return r;
}
__device__ __forceinline__ float ex2f(float x) {
    float r;
    asm("ex2.approx.f32 %0, %1;" : "=f"(r) : "f"(x));
    return r;
}

// ---------------- scratch (device globals) ----------------------------------
__device__ __nv_bfloat16 g_hhi [NROWS*DD], g_hlo [NROWS*DD];
__device__ __half        g_hh16[NROWS*DD];
__device__ __nv_bfloat16 g_qhi [NROWS*DD], g_qlo [NROWS*DD];
__device__ __nv_bfloat16 g_khi [NROWS*DD], g_klo [NROWS*DD];
__device__ __half        g_vh  [NROWS*DD];
__device__ __half        g_ch  [NROWS*DD];
__device__ float         g_x2  [NROWS*DD];
__device__ __half        g_h2h [NROWS*DD];
__device__ __half        g_ffh [NROWS*FF];
__device__ __nv_bfloat16 g_wqhi[DD*DD], g_wqlo[DD*DD];
__device__ __nv_bfloat16 g_wkhi[DD*DD], g_wklo[DD*DD];
__device__ __half        g_wv16[DD*DD];
__device__ __half        g_wo16[DD*DD];
__device__ __half        g_w1h [FF*DD];
__device__ __half        g_w2h [DD*FF];

// ---------------- weight conversions -----------------------------------------
struct CvtArgs2 {
    const float* s[2];
    __nv_bfloat16* h[2];
    __nv_bfloat16* l[2];
    float scale[2];
};
__global__ __launch_bounds__(256) void cvt2_kernel(CvtArgs2 a)
{
    int w = blockIdx.y;
    int i = blockIdx.x * 256 + threadIdx.x;
    float sc = a.scale[w];
    float4 v = ((const float4*)a.s[w])[i];
    v.x *= sc; v.y *= sc; v.z *= sc; v.w *= sc;
    __nv_bfloat16 h[4], l[4];
    split_bf16(v.x, h[0], l[0]); split_bf16(v.y, h[1], l[1]);
    split_bf16(v.z, h[2], l[2]); split_bf16(v.w, h[3], l[3]);
    *(uint2*)(a.h[w] + (size_t)i * 4) = *(uint2*)h;
    *(uint2*)(a.l[w] + (size_t)i * 4) = *(uint2*)l;
}
struct CvtArgsH {
    const float* s[4];
    __half* o[4];
    int n4[4];
};
__global__ __launch_bounds__(256) void cvt4h_kernel(CvtArgsH a)
{
    int w = blockIdx.y;
    int i = blockIdx.x * 256 + threadIdx.x;
    if (i >= a.n4[w]) return;
    float4 v = ((const float4*)a.s[w])[i];
    __half o[4];
    o[0] = __float2half_rn(v.x); o[1] = __float2half_rn(v.y);
    o[2] = __float2half_rn(v.z); o[3] = __float2half_rn(v.w);
    *(uint2*)(a.o[w] + (size_t)i * 4) = *(uint2*)o;
}

// ---------------- RMSNorm: writes hi/lo bf16 + fp16 single -------------------
__global__ __launch_bounds__(256) void rmsnorm_kernel(
    const float* __restrict__ x, const float* __restrict__ w,
    __nv_bfloat16* __restrict__ ohi, __nv_bfloat16* __restrict__ olo,
    __half* __restrict__ oh16)
{
    int row = blockIdx.x;
    const float* xr = x + (size_t)row * DD;
    int t = threadIdx.x;
    float v0 = xr[t];
    float v1 = xr[t + 256];
    float ss = v0 * v0 + v1 * v1;
    #pragma unroll
    for (int off = 16; off; off >>= 1)
        ss += __shfl_xor_sync(0xffffffffu, ss, off);
    __shared__ float red[8];
    if ((t & 31) == 0) red[t >> 5] = ss;
    __syncthreads();
    float total = 0.f;
    #pragma unroll
    for (int i = 0; i < 8; i++) total += red[i];
    float inv = rsqrtf(total * (1.0f / DD) + 1e-6f);
    float o0 = w[t] * v0 * inv;
    float o1 = w[t + 256] * v1 * inv;
    __nv_bfloat16 h, l;
    size_t base = (size_t)row * DD;
    split_bf16(o0, h, l); ohi[base + t] = h;       olo[base + t] = l;
    split_bf16(o1, h, l); ohi[base + t + 256] = h; olo[base + t + 256] = l;
    oh16[base + t]       = __float2half_rn(o0);
    oh16[base + t + 256] = __float2half_rn(o1);
}

// ---------------- RMSNorm: writes fp16 single --------------------------------
__global__ __launch_bounds__(256) void rmsnorm_h_kernel(
    const float* __restrict__ x, const float* __restrict__ w,
    __half* __restrict__ oh)
{
    int row = blockIdx.x;
    const float* xr = x + (size_t)row * DD;
    int t = threadIdx.x;
    float v0 = xr[t];
    float v1 = xr[t + 256];
    float ss = v0 * v0 + v1 * v1;
    #pragma unroll
    for (int off = 16; off; off >>= 1)
        ss += __shfl_xor_sync(0xffffffffu, ss, off);
    __shared__ float red[8];
    if ((t & 31) == 0) red[t >> 5] = ss;
    __syncthreads();
    float total = 0.f;
    #pragma unroll
    for (int i = 0; i < 8; i++) total += red[i];
    float inv = rsqrtf(total * (1.0f / DD) + 1e-6f);
    size_t base = (size_t)row * DD;
    oh[base + t]       = __float2half_rn(w[t] * v0 * inv);
    oh[base + t + 256] = __float2half_rn(w[t + 256] * v1 * inv);
}

// ---------------- split-bf16 tensor-core GEMM (mma.sync) ---------------------
// C[M,N] = A[M,K] @ B[N,K]^T -> bf16 hi/lo.  (Q/K projections)
#define STG 65536
#define OFF_ALO 16384
#define OFF_BHI 32768
#define OFF_BLO 49152
#define TSWZ(r, c16) ((uint32_t)((r) * 128 + (((c16) ^ ((r) & 7)) << 4)))

__global__ __launch_bounds__(256) void gemm_mma_kernel(
    const __nv_bfloat16* __restrict__ Ahi, const __nv_bfloat16* __restrict__ Alo,
    const __nv_bfloat16* __restrict__ Bhi, const __nv_bfloat16* __restrict__ Blo,
    __nv_bfloat16* __restrict__ Chi, __nv_bfloat16* __restrict__ Clo,
    int N, int K)
{
    extern __shared__ char smem[];
    uint32_t sb = smem_to_u32(smem);
    int tid = threadIdx.x;
    int wid = tid >> 5, lane = tid & 31;
    int bm = blockIdx.y * 128, bn = blockIdx.x * 128;

    int lr0 = tid >> 3, lc = tid & 7;
    uint32_t soff[4];
    uint32_t ofsA[4], ofsB[4];
    #pragma unroll
    for (int it = 0; it < 4; it++) {
        int r = lr0 + it * 32;
        soff[it] = TSWZ(r, lc);
        ofsA[it] = (uint32_t)((bm + r) * K + lc * 8);
        ofsB[it] = (uint32_t)((bn + r) * K + lc * 8);
    }

    #define ISSUE(s, kt) do {                                                   \
        uint32_t _b = sb + (uint32_t)(s) * STG;                                 \
        uint32_t _ko = (uint32_t)(kt) * 64;                                     \
        _Pragma("unroll")                                                       \
        for (int _it = 0; _it < 4; _it++) {                                     \
            cpasync16(_b + soff[_it],           Ahi + ofsA[_it] + _ko);         \
            cpasync16(_b + OFF_ALO + soff[_it], Alo + ofsA[_it] + _ko);         \
            cpasync16(_b + OFF_BHI + soff[_it], Bhi + ofsB[_it] + _ko);         \
            cpasync16(_b + OFF_BLO + soff[_it], Blo + ofsB[_it] + _ko);         \
        }                                                                       \
        cpasync_commit();                                                       \
    } while (0)

    float acc[2][8][4];
    #pragma unroll
    for (int ma = 0; ma < 2; ma++)
        #pragma unroll
        for (int na = 0; na < 8; na++)
            #pragma unroll
            for (int j = 0; j < 4; j++) acc[ma][na][j] = 0.f;

    int wm = wid & 3, wn = wid >> 2;
    int arow = wm * 32 + (lane & 15);
    int ac16 = lane >> 4;
    int brow = wn * 64 + (lane & 7) + ((lane >> 4) & 1) * 8;
    int bc16 = (lane >> 3) & 1;

    const int NC = K >> 6;
    ISSUE(0, 0);

    #pragma unroll 1
    for (int kt = 0; kt < NC; kt++) {
        if (kt + 1 < NC) { ISSUE((kt + 1) & 1, kt + 1); cpasync_wait1(); }
        else             { cpasync_wait0(); }
        __syncthreads();

        uint32_t ab = sb + (uint32_t)(kt & 1) * STG;
        #pragma unroll
        for (int kk = 0; kk < 4; kk++) {
            uint32_t ah[2][4], al[2][4];
            #pragma unroll
            for (int ma = 0; ma < 2; ma++) {
                uint32_t ad = ab + TSWZ(arow + ma * 16, ac16 + kk * 2);
                ldsm4(ah[ma], ad);
                ldsm4(al[ma], ad + OFF_ALO);
            }
            #pragma unroll
            for (int np = 0; np < 4; np++) {
                uint32_t bd = ab + OFF_BHI + TSWZ(brow + np * 16, bc16 + kk * 2);
                uint32_t bh[4], bl[4];
                ldsm4(bh, bd);
                ldsm4(bl, bd + 16384);
                #pragma unroll
                for (int ma = 0; ma < 2; ma++) {
                    mma16816(acc[ma][np*2],   ah[ma], bh);
                    mma16816(acc[ma][np*2+1], ah[ma], bh + 2);
                    mma16816(acc[ma][np*2],   ah[ma], bl);
                    mma16816(acc[ma][np*2+1], ah[ma], bl + 2);
                    mma16816(acc[ma][np*2],   al[ma], bh);
                    mma16816(acc[ma][np*2+1], al[ma], bh + 2);
                }
            }
        }
        __syncthreads();
    }

    // epilogue
    int g = lane >> 2, tg = lane & 3;
    #pragma unroll
    for (int ma = 0; ma < 2; ma++) {
        #pragma unroll
        for (int na = 0; na < 8; na++) {
            int row = bm + wm * 32 + ma * 16 + g;
            int col = bn + wn * 64 + na * 8 + tg * 2;
            float* c = acc[ma][na];
            size_t o0 = (size_t)row * N + col;
            size_t o1 = (size_t)(row + 8) * N + col;
            __nv_bfloat16 h0[2], l0[2], h1[2], l1[2];
            split_bf16(c[0], h0[0], l0[0]); split_bf16(c[1], h0[1], l0[1]);
            split_bf16(c[2], h1[0], l1[0]); split_bf16(c[3], h1[1], l1[1]);
            *(uint32_t*)(Chi + o0) = *(uint32_t*)h0;
            *(uint32_t*)(Clo + o0) = *(uint32_t*)l0;
            *(uint32_t*)(Chi + o1) = *(uint32_t*)h1;
            *(uint32_t*)(Clo + o1) = *(uint32_t*)l1;
        }
    }
    #undef ISSUE
}

// ---------------- single-fp16 tensor-core GEMM -------------------------------
// EPI: 0 = fp16 out   1 = relu -> fp16   2 = +R -> fp32
#define HSTG 32768
#define H_B  16384

template <int EPI>
__global__ __launch_bounds__(256) void gemm_h_kernel(
    const __half* __restrict__ A, const __half* __restrict__ B,
    const float* __restrict__ R, float* __restrict__ Cf,
    __half* __restrict__ Ch, int N, int K)
{
    extern __shared__ char smem[];
    uint32_t sb = smem_to_u32(smem);
    int tid = threadIdx.x;
    int wid = tid >> 5, lane = tid & 31;
    int bm = blockIdx.y * 128, bn = blockIdx.x * 128;

    int lr0 = tid >> 3, lc = tid & 7;
    uint32_t soff[4];
    uint32_t ofsA[4], ofsB[4];
    #pragma unroll
    for (int it = 0; it < 4; it++) {
        int r = lr0 + it * 32;
        soff[it] = TSWZ(r, lc);
        ofsA[it] = (uint32_t)((bm + r) * K + lc * 8);
        ofsB[it] = (uint32_t)((bn + r) * K + lc * 8);
    }

    #define HISSUE(s, kt) do {                                                  \
        uint32_t _b = sb + (uint32_t)(s) * HSTG;                                \
        uint32_t _ko = (uint32_t)(kt) * 64;                                     \
        _Pragma("unroll")                                                       \
        for (int _it = 0; _it < 4; _it++) {                                     \
            cpasync16(_b + soff[_it],        A + ofsA[_it] + _ko);              \
            cpasync16(_b + H_B + soff[_it],  B + ofsB[_it] + _ko);              \
        }                                                                       \
        cpasync_commit();                                                       \
    } while (0)

    float acc[2][8][4];
    #pragma unroll
    for (int ma = 0; ma < 2; ma++)
        #pragma unroll
        for (int na = 0; na < 8; na++)
            #pragma unroll
            for (int j = 0; j < 4; j++) acc[ma][na][j] = 0.f;

    int wm = wid & 3, wn = wid >> 2;
    int arow = wm * 32 + (lane & 15);
    int ac16 = lane >> 4;
    int brow = wn * 64 + (lane & 7) + ((lane >> 4) & 1) * 8;
    int bc16 = (lane >> 3) & 1;

    const int NC = K >> 6;
    HISSUE(0, 0);

    #pragma unroll 1
    for (int kt = 0; kt < NC; kt++) {
        if (kt + 1 < NC) { HISSUE((kt + 1) & 1, kt + 1); cpasync_wait1(); }
        else             { cpasync_wait0(); }
        __syncthreads();

        uint32_t ab = sb + (uint32_t)(kt & 1) * HSTG;
        #pragma unroll
        for (int kk = 0; kk < 4; kk++) {
            uint32_t ah[2][4];
            #pragma unroll
            for (int ma = 0; ma < 2; ma++)
                ldsm4(ah[ma], ab + TSWZ(arow + ma * 16, ac16 + kk * 2));
            #pragma unroll
            for (int np = 0; np < 4; np++) {
                uint32_t bh[4];
                ldsm4(bh, ab + H_B + TSWZ(brow + np * 16, bc16 + kk * 2));
                #pragma unroll
                for (int ma = 0; ma < 2; ma++) {
                    mma16816h(acc[ma][np*2],   ah[ma], bh);
                    mma16816h(acc[ma][np*2+1], ah[ma], bh + 2);
                }
            }
        }
        __syncthreads();
    }

    // epilogue
    int g = lane >> 2, tg = lane & 3;
    #pragma unroll
    for (int ma = 0; ma < 2; ma++) {
        #pragma unroll
        for (int na = 0; na < 8; na++) {
            int row = bm + wm * 32 + ma * 16 + g;
            int col = bn + wn * 64 + na * 8 + tg * 2;
            float* c = acc[ma][na];
            size_t o0 = (size_t)row * N + col;
            size_t o1 = (size_t)(row + 8) * N + col;
            if (EPI == 0 || EPI == 1) {
                float v0 = c[0], v1 = c[1], v2 = c[2], v3 = c[3];
                if (EPI == 1) {
                    v0 = fmaxf(v0, 0.f); v1 = fmaxf(v1, 0.f);
                    v2 = fmaxf(v2, 0.f); v3 = fmaxf(v3, 0.f);
                }
                __half h0[2], h1[2];
                h0[0] = __float2half_rn(v0); h0[1] = __float2half_rn(v1);
                h1[0] = __float2half_rn(v2); h1[1] = __float2half_rn(v3);
                *(uint32_t*)(Ch + o0) = *(uint32_t*)h0;
                *(uint32_t*)(Ch + o1) = *(uint32_t*)h1;
            } else {
                float2 v0 = make_float2(c[0], c[1]);
                float2 v1 = make_float2(c[2], c[3]);
                float2 r0 = *(const float2*)(R + o0);
                float2 r1 = *(const float2*)(R + o1);
                v0.x += r0.x; v0.y += r0.y;
                v1.x += r1.x; v1.y += r1.y;
                *(float2*)(Cf + o0) = v0;
                *(float2*)(Cf + o1) = v1;
            }
        }
    }
    #undef HISSUE
}

// ---------------- tensor-core flash attention --------------------------------
// Q bf16 hi/lo (pre-scaled log2e), K bf16 hi/lo, V fp16 single,
// ctx fp16 single. Bias direct LDG. SMEM 80 KB -> 2 CTAs/SM.
#define AQ_HI 0u
#define AQ_LO 16384u
#define AKV0  32768u
#define AKV_STG 24576u
#define A_SMEM (32768u + 2u*24576u)

__global__ __launch_bounds__(256, 2) void attn_mma_kernel(
    const __nv_bfloat16* __restrict__ Qhi, const __nv_bfloat16* __restrict__ Qlo,
    const __nv_bfloat16* __restrict__ Khi, const __nv_bfloat16* __restrict__ Klo,
    const __half* __restrict__ Vh,
    const float* __restrict__ bias,
    __half* __restrict__ ch)
{
    extern __shared__ char smem[];
    uint32_t sb = smem_to_u32(smem);
    int tid = threadIdx.x, wid = tid >> 5, lane = tid & 31;
    int qt = blockIdx.x, h = blockIdx.y, b = blockIdx.z;

    // ---- Q load ----
    {
        int r = tid >> 1;
        int cb = (tid & 1) * 4;
        size_t grow = ((size_t)(b * SS + qt * 128 + r)) * DD + h * HD;
        #pragma unroll
        for (int i = 0; i < 4; i++) {
            int c16 = cb + i;
            uint32_t so = TSWZ(r, c16);
            cpasync16(sb + AQ_HI + so, Qhi + grow + c16 * 8);
            cpasync16(sb + AQ_LO + so, Qlo + grow + c16 * 8);
        }
        cpasync_commit();
    }
    // ---- KV tile issue ----
    int kvr = tid & 63;
    int kvcb = (tid >> 6) * 2;
    #define ISSUE_KV(kt, stg) do {                                              \
        uint32_t _bse = sb + AKV0 + (uint32_t)(stg) * AKV_STG;                  \
        size_t _gr = ((size_t)(b * SS + (kt) * 64 + kvr)) * DD + h * HD;        \
        _Pragma("unroll")                                                       \
        for (int _i = 0; _i < 2; _i++) {                                        \
            int _c = kvcb + _i;                                                 \
            uint32_t _so = TSWZ(kvr, _c);                                       \
            cpasync16(_bse + _so,          Khi + _gr + _c * 8);                 \
            cpasync16(_bse + 8192 + _so,   Klo + _gr + _c * 8);                 \
            cpasync16(_bse + 16384 + _so,  Vh  + _gr + _c * 8);                 \
        }                                                                       \
        cpasync_commit();                                                       \
    } while (0)

    ISSUE_KV(0, 0);

    float oacc[8][4];
    #pragma unroll
    for (int na = 0; na < 8; na++)
        #pragma unroll
        for (int j = 0; j < 4; j++) oacc[na][j] = 0.f;
    float lacc[4] = {0.f, 0.f, 0.f, 0.f};
    float m0 = -1e30f, m1 = -1e30f;
    const uint32_t bones[2] = {0x3C003C00u, 0x3C003C00u};

    int arow = wid * 16 + (lane & 15);
    int ac16 = lane >> 4;
    int bro  = (lane & 7) + ((lane >> 4) & 1) * 8;
    int bc16 = (lane >> 3) & 1;
    int vro  = lane & 15;
    int vch  = lane >> 4;

    size_t brow0 = ((size_t)(b * HH + h) * SS + (qt * 128 + wid * 16 + (lane >> 2))) * SS
                   + 2 * (lane & 3);
    size_t brow1 = brow0 + 8 * (size_t)SS;

    #pragma unroll 1
    for (int kt = 0; kt < 16; kt++) {
        if (kt + 1 < 16) { ISSUE_KV(kt + 1, (kt + 1) & 1); cpasync_wait1(); }
        else             { cpasync_wait0(); }
        __syncthreads();
        uint32_t kvb = sb + AKV0 + (uint32_t)(kt & 1) * AKV_STG;

        // ---- S = Q K^T (split: 3 terms) ----
        float sacc[8][4];
        #pragma unroll
        for (int na = 0; na < 8; na++)
            #pragma unroll
            for (int j = 0; j < 4; j++) sacc[na][j] = 0.f;
        #pragma unroll
        for (int kk = 0; kk < 4; kk++) {
            uint32_t ah[4], al[4];
            uint32_t ad = sb + AQ_HI + TSWZ(arow, ac16 + kk * 2);
            ldsm4(ah, ad);
            ldsm4(al, ad + AQ_LO);
            #pragma unroll
            for (int ng = 0; ng < 4; ng++) {
                uint32_t bd = kvb + TSWZ(bro + ng * 16, bc16 + kk * 2);
                uint32_t kh[4], kl[4];
                ldsm4(kh, bd);
                ldsm4(kl, bd + 8192);
                mma16816(sacc[ng*2],   ah, kh);
                mma16816(sacc[ng*2+1], ah, kh + 2);
                mma16816(sacc[ng*2],   ah, kl);
                mma16816(sacc[ng*2+1], ah, kl + 2);
                mma16816(sacc[ng*2],   al, kh);
                mma16816(sacc[ng*2+1], al, kh + 2);
            }
        }

        // ---- bias (x log2e) + max ----
        const float* bp0 = bias + brow0 + kt * 64;
        const float* bp1 = bias + brow1 + kt * 64;
        float tm0 = -1e30f, tm1 = -1e30f;
        #pragma unroll
        for (int na = 0; na < 8; na++) {
            float2 bv0 = *(const float2*)(bp0 + na * 8);
            float2 bv1 = *(const float2*)(bp1 + na * 8);
            sacc[na][0] = fmaf(bv0.x, L2E, sacc[na][0]);
            sacc[na][1] = fmaf(bv0.y, L2E, sacc[na][1]);
            sacc[na][2] = fmaf(bv1.x, L2E, sacc[na][2]);
            sacc[na][3] = fmaf(bv1.y, L2E, sacc[na][3]);
            tm0 = fmaxf(tm0, fmaxf(sacc[na][0], sacc[na][1]));
            tm1 = fmaxf(tm1, fmaxf(sacc[na][2], sacc[na][3]));
        }
        tm0 = fmaxf(tm0, __shfl_xor_sync(0xffffffffu, tm0, 1));
        tm0 = fmaxf(tm0, __shfl_xor_sync(0xffffffffu, tm0, 2));
        tm1 = fmaxf(tm1, __shfl_xor_sync(0xffffffffu, tm1, 1));
        tm1 = fmaxf(tm1, __shfl_xor_sync(0xffffffffu, tm1, 2));
        float mn0 = fmaxf(m0, tm0), mn1 = fmaxf(m1, tm1);

        if (mn0 != m0 || mn1 != m1) {
            float c0 = ex2f(m0 - mn0), c1 = ex2f(m1 - mn1);
            #pragma unroll
            for (int na = 0; na < 8; na++) {
                oacc[na][0] *= c0; oacc[na][1] *= c0;
                oacc[na][2] *= c1; oacc[na][3] *= c1;
            }
            lacc[0] *= c0; lacc[2] *= c1;
            m0 = mn0; m1 = mn1;
        }

        // ---- p = 2^(t - m) via f16x2; results are P fp16 A-fragments ----
        uint32_t pf[4][4];
        #pragma unroll
        for (int kk = 0; kk < 4; kk++) {
            int n0 = 2 * kk, n1 = 2 * kk + 1;
            pf[kk][0] = ex2h2(packh(sacc[n0][0] - mn0, sacc[n0][1] - mn0));
            pf[kk][1] = ex2h2(packh(sacc[n0][2] - mn1, sacc[n0][3] - mn1));
            pf[kk][2] = ex2h2(packh(sacc[n1][0] - mn0, sacc[n1][1] - mn0));
            pf[kk][3] = ex2h2(packh(sacc[n1][2] - mn1, sacc[n1][3] - mn1));
        }

        // ---- l += row-sums of P ----
        #pragma unroll
        for (int kk = 0; kk < 4; kk++)
            mma16816h(lacc, pf[kk], bones);

        // ---- O += P V (V fp16 single, 1 term) ----
        #pragma unroll
        for (int kk = 0; kk < 4; kk++) {
            #pragma unroll
            for (int j = 0; j < 4; j++) {
                uint32_t vd = kvb + 16384 + TSWZ(kk * 16 + vro, 2 * j + vch);
                uint32_t vh[4];
                ldsm4t(vh, vd);
                mma16816h(oacc[j*2],   pf[kk], vh);
                mma16816h(oacc[j*2+1], pf[kk], vh + 2);
            }
        }
        __syncthreads();
    }

    // ---- epilogue: ctx = O / l, write fp16 single ----
    float il0 = 1.0f / lacc[0], il1 = 1.0f / lacc[2];
    int row0 = b * SS + qt * 128 + wid * 16 + (lane >> 2);
    int colb = h * HD + 2 * (lane & 3);
    #pragma unroll
    for (int na = 0; na < 8; na++) {
        size_t o0 = (size_t)row0 * DD + colb + na * 8;
        size_t o1 = o0 + 8 * (size_t)DD;
        __half hh[2];
        hh[0] = __float2half_rn(oacc[na][0] * il0);
        hh[1] = __float2half_rn(oacc[na][1] * il0);
        *(uint32_t*)(ch + o0) = *(uint32_t*)hh;
        hh[0] = __float2half_rn(oacc[na][2] * il1);
        hh[1] = __float2half_rn(oacc[na][3] * il1);
        *(uint32_t*)(ch + o1) = *(uint32_t*)hh;
    }
    #undef ISSUE_KV
}

// ---------------- stream/event context (created at static init, pre-harness) -
struct StreamCtx {
    cudaStream_t s1 = 0, s2 = 0;
    cudaEvent_t e0 = 0, eR = 0, eC4 = 0, eC2 = 0, eK = 0, eV = 0;
    bool ok = false;
    StreamCtx() {
        ok = cudaStreamCreateWithFlags(&s1, cudaStreamNonBlocking) == cudaSuccess
          && cudaStreamCreateWithFlags(&s2, cudaStreamNonBlocking) == cudaSuccess
          && cudaEventCreateWithFlags(&e0,  cudaEventDisableTiming) == cudaSuccess
          && cudaEventCreateWithFlags(&eR,  cudaEventDisableTiming) == cudaSuccess
          && cudaEventCreateWithFlags(&eC4, cudaEventDisableTiming) == cudaSuccess
          && cudaEventCreateWithFlags(&eC2, cudaEventDisableTiming) == cudaSuccess
          && cudaEventCreateWithFlags(&eK,  cudaEventDisableTiming) == cudaSuccess
          && cudaEventCreateWithFlags(&eV,  cudaEventDisableTiming) == cudaSuccess;
    }
};
static StreamCtx g_sc;

// ---------------- launch -----------------------------------------------------
extern "C" void kernel_launch(void* const* d_in, const int* in_sizes, int n_in,
                              void* d_out, int out_size)
{
    const float* Wk   = (const float*)d_in[0];
    const float* Wo   = (const float*)d_in[1];
    const float* Wq   = (const float*)d_in[2];
    const float* Wv   = (const float*)d_in[3];
    const float* ln1  = (const float*)d_in[4];
    const float* W1   = (const float*)d_in[5];
    const float* W2   = (const float*)d_in[6];
    const float* ln2  = (const float*)d_in[7];
    const float* x    = (const float*)d_in[8];
    const float* bias = (const float*)d_in[9];
    float* out = (float*)d_out;

    #define SYM(p, s) void* p; cudaGetSymbolAddress(&p, s)
    SYM(hhi, g_hhi);  SYM(hlo, g_hlo);  SYM(hh16, g_hh16);
    SYM(qhi, g_qhi);  SYM(qlo, g_qlo);
    SYM(khi, g_khi);  SYM(klo, g_klo);
    SYM(vh, g_vh);    SYM(ch, g_ch);
    SYM(px2, g_x2);
    SYM(h2h, g_h2h);  SYM(ffh, g_ffh);
    SYM(wqh, g_wqhi); SYM(wql, g_wqlo);
    SYM(wkh, g_wkhi); SYM(wkl, g_wklo);
    SYM(wv16, g_wv16); SYM(wo16, g_wo16);
    SYM(w1h, g_w1h);  SYM(w2h, g_w2h);
    #undef SYM

    static bool attr_set = false;
    if (!attr_set) {
        cudaFuncSetAttribute(gemm_mma_kernel, cudaFuncAttributeMaxDynamicSharedMemorySize, 2*STG);
        cudaFuncSetAttribute(gemm_h_kernel<0>, cudaFuncAttributeMaxDynamicSharedMemorySize, 2*HSTG);
        cudaFuncSetAttribute(gemm_h_kernel<1>, cudaFuncAttributeMaxDynamicSharedMemorySize, 2*HSTG);
        cudaFuncSetAttribute(gemm_h_kernel<2>, cudaFuncAttributeMaxDynamicSharedMemorySize, 2*HSTG);
        cudaFuncSetAttribute(attn_mma_kernel, cudaFuncAttributeMaxDynamicSharedMemorySize, A_SMEM);
        attr_set = true;
    }

    typedef const __nv_bfloat16* cbf;
    typedef __nv_bfloat16* bf;
    typedef const __half* chf;
    typedef __half* hf;

    cudaStream_t s1 = g_sc.ok ? g_sc.s1 : 0;
    cudaStream_t s2 = g_sc.ok ? g_sc.s2 : 0;
    #define REC(ev, st)  do { if (g_sc.ok) cudaEventRecord(g_sc.ev, st); } while (0)
    #define WAITE(st, ev) do { if (g_sc.ok) cudaStreamWaitEvent(st, g_sc.ev, 0); } while (0)

    // fork
    REC(e0, 0);
    WAITE(s1, e0);
    WAITE(s2, e0);

    // cvt2 (Wq*log2e / Wk, split bf16) on s1; cvt4h (W1/W2/Wo/Wv fp16) on s2;
    // rmsnorm1 on 0 (emits bf16 hi/lo + fp16)
    CvtArgs2 c2;
    c2.s[0] = Wq; c2.h[0] = (bf)wqh; c2.l[0] = (bf)wql; c2.scale[0] = L2E;
    c2.s[1] = Wk; c2.h[1] = (bf)wkh; c2.l[1] = (bf)wkl; c2.scale[1] = 1.0f;
    dim3 g2(DD*DD/4/256, 2);
    cvt2_kernel<<<g2, 256, 0, s1>>>(c2);
    CvtArgsH ch4;
    ch4.s[0] = W1; ch4.o[0] = (hf)w1h;  ch4.n4[0] = FF*DD/4;
    ch4.s[1] = W2; ch4.o[1] = (hf)w2h;  ch4.n4[1] = DD*FF/4;
    ch4.s[2] = Wo; ch4.o[2] = (hf)wo16; ch4.n4[2] = DD*DD/4;
    ch4.s[3] = Wv; ch4.o[3] = (hf)wv16; ch4.n4[3] = DD*DD/4;
    dim3 gh(FF*DD/4/256, 4);
    cvt4h_kernel<<<gh, 256, 0, s2>>>(ch4);
    rmsnorm_kernel<<<NROWS, 256>>>(x, ln1, (bf)hhi, (bf)hlo, (hf)hh16);
    REC(eR, 0);
    REC(eC4, s1);
    REC(eC2, s2);

    // QKV: Q on 0 (needs cvt2), K on s1 (needs rmsnorm), V on s2 (needs rmsnorm)
    WAITE(0, eC4);
    WAITE(s1, eR);
    WAITE(s2, eR);
    dim3 gD(DD/128, NROWS/128);
    gemm_mma_kernel<<<gD, 256, 2*STG, 0>>>((cbf)hhi, (cbf)hlo, (cbf)wqh, (cbf)wql,
                                           (bf)qhi, (bf)qlo, DD, DD);
    gemm_mma_kernel<<<gD, 256, 2*STG, s1>>>((cbf)hhi, (cbf)hlo, (cbf)wkh, (cbf)wkl,
                                            (bf)khi, (bf)klo, DD, DD);
    gemm_h_kernel<0><<<gD, 256, 2*HSTG, s2>>>((chf)hh16, (chf)wv16,
                                              nullptr, nullptr, (hf)vh, DD, DD);
    REC(eK, s1);
    REC(eV, s2);
    WAITE(0, eK);
    WAITE(0, eV);

    // attention -> ctx fp16 single (2 CTAs/SM)
    dim3 ga(SS/128, HH, BB);
    attn_mma_kernel<<<ga, 256, A_SMEM>>>((cbf)qhi, (cbf)qlo, (cbf)khi, (cbf)klo,
                                         (chf)vh, bias, (hf)ch);

    // x2 = x + ctx @ Wo^T (fp16 single -> fp32)
    WAITE(0, eC2);
    gemm_h_kernel<2><<<gD, 256, 2*HSTG>>>((chf)ch, (chf)wo16,
                                          x, (float*)px2, nullptr, DD, DD);

    // h2 = rmsnorm(x2, ln2) -> fp16 single
    rmsnorm_h_kernel<<<NROWS, 256>>>((const float*)px2, ln2, (hf)h2h);

    // FFN
    dim3 gF(FF/128, NROWS/128);
    gemm_h_kernel<1><<<gF, 256, 2*HSTG>>>((chf)h2h, (chf)w1h,
                                          nullptr, nullptr, (hf)ffh, FF, DD);
    gemm_h_kernel<2><<<gD, 256, 2*HSTG>>>((chf)ffh, (chf)w2h,
                                          (const float*)px2, out, nullptr, DD, FF);
    #undef REC
    #undef WAITE
}